// round 1
// baseline (speedup 1.0000x reference)
#include <cuda_runtime.h>
#include <math.h>

// ---------------------------------------------------------------------------
// LoRA attention, fp32 pipeline.
// B=4, S=2048, E=1024, R=16.  M = B*S = 8192.
// ---------------------------------------------------------------------------

#define BM 128
#define BN 128
#define BKD 16
#define TM 8
#define TN 8

// Scratch (device globals; no allocations allowed).
__device__ float g_XAq[8192 * 16];
__device__ float g_XAk[8192 * 16];
__device__ float g_XAv[8192 * 16];
__device__ float g_Q[8192 * 1024];
__device__ float g_K[8192 * 1024];
__device__ float g_V[8192 * 1024];
__device__ float g_S[4 * 2048 * 2048];   // 64 MB scores
__device__ float g_O[8192 * 1024];

// ---------------------------------------------------------------------------
// Rank-16 projection: XA[m][r] = sum_e X[m][e] * Aw[r][e].
// One warp per row m. Aw is 16x1024 (64KB), stays hot in L1.
// ---------------------------------------------------------------------------
__global__ void lora_xa_kernel(const float* __restrict__ X,
                               const float* __restrict__ Aw,
                               float* __restrict__ XA, int K) {
    int warp = (blockIdx.x * blockDim.x + threadIdx.x) >> 5;
    int lane = threadIdx.x & 31;
    const float* x = X + (long long)warp * K;
    float acc[16];
#pragma unroll
    for (int r = 0; r < 16; r++) acc[r] = 0.f;
    for (int e = lane; e < K; e += 32) {
        float xv = x[e];
#pragma unroll
        for (int r = 0; r < 16; r++) acc[r] += xv * Aw[r * K + e];
    }
#pragma unroll
    for (int r = 0; r < 16; r++) {
#pragma unroll
        for (int off = 16; off; off >>= 1)
            acc[r] += __shfl_xor_sync(0xFFFFFFFFu, acc[r], off);
    }
    if (lane == 0) {
#pragma unroll
        for (int r = 0; r < 16; r++) XA[(long long)warp * 16 + r] = acc[r];
    }
}

// ---------------------------------------------------------------------------
// Tiled SGEMM.
//   TRANS_B = true  (NT): C[m][n] = alpha * sum_k A[m][k] * B[n][k]   (B is [N,K])
//   TRANS_B = false (NN): C[m][n] = alpha * sum_k A[m][k] * B[k][n]   (B is [K,N])
// Optional fused LoRA epilogue: C += sum_{r<16} loraX[m][r] * loraW[n][r].
// Batched along gridDim.z with given strides. All dims divide tiles evenly.
// ---------------------------------------------------------------------------
template <bool TRANS_B>
__global__ __launch_bounds__(256)
void sgemm_kernel(const float* __restrict__ A, const float* __restrict__ B,
                  float* __restrict__ C, int M, int N, int K,
                  long long strideA, long long strideB, long long strideC,
                  float alpha,
                  const float* __restrict__ loraX,
                  const float* __restrict__ loraW) {
    __shared__ float As[BKD][BM];
    __shared__ float Bs[BKD][BN];

    const int m0 = blockIdx.y * BM;
    const int n0 = blockIdx.x * BN;
    const int z = blockIdx.z;

    A += (long long)z * strideA + (long long)m0 * K;
    if (TRANS_B)
        B += (long long)z * strideB + (long long)n0 * K;
    else
        B += (long long)z * strideB + n0;
    C += (long long)z * strideC;

    const int tid = threadIdx.x;
    const int tRow = tid >> 4;   // 0..15
    const int tCol = tid & 15;   // 0..15

    float acc[TM][TN];
#pragma unroll
    for (int i = 0; i < TM; i++)
#pragma unroll
        for (int j = 0; j < TN; j++) acc[i][j] = 0.f;

    for (int k0 = 0; k0 < K; k0 += BKD) {
        // ---- load A tile (128 rows x 16 k), transposed into As[k][m] ----
#pragma unroll
        for (int it = 0; it < 2; it++) {
            int idx = tid + it * 256;          // 0..511
            int row = idx >> 2;                // 0..127
            int kq = (idx & 3) << 2;           // 0,4,8,12
            float4 v = *reinterpret_cast<const float4*>(
                &A[(long long)row * K + k0 + kq]);
            As[kq + 0][row] = v.x;
            As[kq + 1][row] = v.y;
            As[kq + 2][row] = v.z;
            As[kq + 3][row] = v.w;
        }
        // ---- load B tile into Bs[k][n] ----
        if (TRANS_B) {
#pragma unroll
            for (int it = 0; it < 2; it++) {
                int idx = tid + it * 256;
                int row = idx >> 2;            // n index 0..127
                int kq = (idx & 3) << 2;
                float4 v = *reinterpret_cast<const float4*>(
                    &B[(long long)row * K + k0 + kq]);
                Bs[kq + 0][row] = v.x;
                Bs[kq + 1][row] = v.y;
                Bs[kq + 2][row] = v.z;
                Bs[kq + 3][row] = v.w;
            }
        } else {
#pragma unroll
            for (int it = 0; it < 2; it++) {
                int idx = tid + it * 256;
                int krow = idx >> 5;           // 0..15
                int nq = (idx & 31) << 2;      // 0..124
                float4 v = *reinterpret_cast<const float4*>(
                    &B[(long long)(k0 + krow) * N + nq]);
                *reinterpret_cast<float4*>(&Bs[krow][nq]) = v;
            }
        }
        __syncthreads();

        // ---- compute ----
#pragma unroll
        for (int k = 0; k < BKD; k++) {
            float a[TM], b[TN];
#pragma unroll
            for (int i = 0; i < TM; i++) a[i] = As[k][tRow * TM + i];
#pragma unroll
            for (int j = 0; j < TN; j++) b[j] = Bs[k][tCol * TN + j];
#pragma unroll
            for (int i = 0; i < TM; i++)
#pragma unroll
                for (int j = 0; j < TN; j++) acc[i][j] += a[i] * b[j];
        }
        __syncthreads();
    }

    // ---- epilogue ----
#pragma unroll
    for (int i = 0; i < TM; i++) {
        int r = m0 + tRow * TM + i;
        if (loraX != nullptr) {
            float xa[16];
#pragma unroll
            for (int t = 0; t < 16; t++) xa[t] = loraX[(long long)r * 16 + t];
#pragma unroll
            for (int j = 0; j < TN; j++) {
                int c = n0 + tCol * TN + j;
                float d = 0.f;
#pragma unroll
                for (int t = 0; t < 16; t++) d += xa[t] * loraW[(long long)c * 16 + t];
                C[(long long)r * N + c] = alpha * acc[i][j] + d;
            }
        } else {
#pragma unroll
            for (int j = 0; j < TN; j++) {
                int c = n0 + tCol * TN + j;
                C[(long long)r * N + c] = alpha * acc[i][j];
            }
        }
    }
}

// ---------------------------------------------------------------------------
// Row softmax over 2048 columns. One block (256 threads) per row; values held
// in registers across max/exp/sum/normalize (single global read + write).
// ---------------------------------------------------------------------------
__global__ void softmax_rows_kernel(float* __restrict__ S) {
    const int NCOL = 2048;
    const int VPT = 8;  // 2048 / 256
    float* row = S + (long long)blockIdx.x * NCOL;
    int tid = threadIdx.x;

    float v[VPT];
    float mx = -INFINITY;
#pragma unroll
    for (int i = 0; i < VPT; i++) {
        v[i] = row[tid + i * 256];
        mx = fmaxf(mx, v[i]);
    }
    __shared__ float red[256];
    red[tid] = mx;
    __syncthreads();
#pragma unroll
    for (int s = 128; s > 0; s >>= 1) {
        if (tid < s) red[tid] = fmaxf(red[tid], red[tid + s]);
        __syncthreads();
    }
    mx = red[0];
    __syncthreads();

    float sum = 0.f;
#pragma unroll
    for (int i = 0; i < VPT; i++) {
        v[i] = __expf(v[i] - mx);
        sum += v[i];
    }
    red[tid] = sum;
    __syncthreads();
#pragma unroll
    for (int s = 128; s > 0; s >>= 1) {
        if (tid < s) red[tid] += red[tid + s];
        __syncthreads();
    }
    float inv = 1.f / red[0];
#pragma unroll
    for (int i = 0; i < VPT; i++) row[tid + i * 256] = v[i] * inv;
}

// ---------------------------------------------------------------------------
// Launch
// ---------------------------------------------------------------------------
extern "C" void kernel_launch(void* const* d_in, const int* in_sizes, int n_in,
                              void* d_out, int out_size) {
    const float* query = (const float*)d_in[0];
    const float* key_ = (const float*)d_in[1];
    const float* value = (const float*)d_in[2];
    const float* Qw = (const float*)d_in[3];
    const float* Kw = (const float*)d_in[4];
    const float* Vw = (const float*)d_in[5];
    const float* QA = (const float*)d_in[6];
    const float* QB = (const float*)d_in[7];
    const float* KA = (const float*)d_in[8];
    const float* KB = (const float*)d_in[9];
    const float* VA = (const float*)d_in[10];
    const float* VB = (const float*)d_in[11];
    const float* Ow = (const float*)d_in[12];
    float* out = (float*)d_out;

    const int E = 1024, S = 2048, Bb = 4;
    const int M = Bb * S;  // 8192

    float *pXAq, *pXAk, *pXAv, *pQ, *pK, *pV, *pS, *pO;
    cudaGetSymbolAddress((void**)&pXAq, g_XAq);
    cudaGetSymbolAddress((void**)&pXAk, g_XAk);
    cudaGetSymbolAddress((void**)&pXAv, g_XAv);
    cudaGetSymbolAddress((void**)&pQ, g_Q);
    cudaGetSymbolAddress((void**)&pK, g_K);
    cudaGetSymbolAddress((void**)&pV, g_V);
    cudaGetSymbolAddress((void**)&pS, g_S);
    cudaGetSymbolAddress((void**)&pO, g_O);

    // 1) LoRA low-rank projections: XA = X @ A^T  (8192 x 16)
    lora_xa_kernel<<<M / 8, 256>>>(query, QA, pXAq, E);
    lora_xa_kernel<<<M / 8, 256>>>(key_, KA, pXAk, E);
    lora_xa_kernel<<<M / 8, 256>>>(value, VA, pXAv, E);

    // 2) Q/K/V projections (NT) with fused LoRA epilogue
    dim3 gproj(E / BN, M / BM, 1);
    sgemm_kernel<true><<<gproj, 256>>>(query, Qw, pQ, M, E, E, 0, 0, 0, 1.f, pXAq, QB);
    sgemm_kernel<true><<<gproj, 256>>>(key_, Kw, pK, M, E, E, 0, 0, 0, 1.f, pXAk, KB);
    sgemm_kernel<true><<<gproj, 256>>>(value, Vw, pV, M, E, E, 0, 0, 0, 1.f, pXAv, VB);

    // 3) scores = Q K^T / sqrt(E)  (batched NT, z = batch)
    dim3 gsc(S / BN, S / BM, Bb);
    sgemm_kernel<true><<<gsc, 256>>>(pQ, pK, pS, S, S, E,
                                     (long long)S * E, (long long)S * E,
                                     (long long)S * S, 1.f / 32.f, nullptr, nullptr);

    // 4) softmax over rows
    softmax_rows_kernel<<<Bb * S, 256>>>(pS);

    // 5) out = attn @ V  (batched NN)
    dim3 gav(E / BN, S / BM, Bb);
    sgemm_kernel<false><<<gav, 256>>>(pS, pV, pO, S, E, S,
                                      (long long)S * S, (long long)S * E,
                                      (long long)S * E, 1.f, nullptr, nullptr);

    // 6) final = out @ O^T  (NT) -> d_out
    sgemm_kernel<true><<<gproj, 256>>>(pO, Ow, out, M, E, E, 0, 0, 0, 1.f,
                                       nullptr, nullptr);
}

// round 10
// speedup vs baseline: 2.4544x; 2.4544x over previous
#include <cuda_runtime.h>
#include <cuda_bf16.h>
#include <math.h>
#include <stdint.h>

// ============================================================================
// LoRA attention via mma.sync (HMMA) split-bf16 3-pass GEMMs.
// Base sm_103 target compatible: NO tcgen05 (toolchain lowers at sm_103).
// B=4, S=2048, E=1024, R=16.  M = B*S = 8192.
// ============================================================================

#define EDIM 1024
#define SDIM 2048
#define BATCH 4
#define MTOT 8192
#define KC 32                    // K elements per chunk
#define ROWB 80                  // padded row stride bytes (32 bf16 = 64B + 16B pad)
#define TILE_B (128 * ROWB)      // 10240 B per 128x32 tile
#define STAGE_B (4 * TILE_B)     // Ahi, Alo, Bhi, Blo = 40960 B
#define SMEM_DYN (2 * STAGE_B)   // 81920 B

typedef __nv_bfloat16 bf16;

static __device__ __forceinline__ uint32_t smem_u32(const void* p) {
    uint32_t a;
    asm("{ .reg .u64 t; cvta.to.shared.u64 t, %1; cvt.u32.u64 %0, t; }"
        : "=r"(a) : "l"(p));
    return a;
}

static __device__ __forceinline__ void cp_async16(uint32_t dst, const void* src) {
    asm volatile("cp.async.cg.shared.global [%0], [%1], 16;"
                 :: "r"(dst), "l"(src) : "memory");
}

static __device__ __forceinline__ void mma_bf16(float* c, const uint32_t* a,
                                                const uint32_t* b) {
    asm volatile(
        "mma.sync.aligned.m16n8k16.row.col.f32.bf16.bf16.f32 "
        "{%0,%1,%2,%3}, {%4,%5,%6,%7}, {%8,%9}, {%0,%1,%2,%3};"
        : "+f"(c[0]), "+f"(c[1]), "+f"(c[2]), "+f"(c[3])
        : "r"(a[0]), "r"(a[1]), "r"(a[2]), "r"(a[3]), "r"(b[0]), "r"(b[1]));
}

// ---------------------------------------------------------------------------
// Scratch (device globals; no allocations allowed).
// ---------------------------------------------------------------------------
__device__ float g_XAq[MTOT * 16];
__device__ float g_XAk[MTOT * 16];
__device__ float g_XAv[MTOT * 16];
__device__ bf16 g_qin_h[MTOT * EDIM], g_qin_l[MTOT * EDIM];
__device__ bf16 g_kin_h[MTOT * EDIM], g_kin_l[MTOT * EDIM];
__device__ bf16 g_vin_h[MTOT * EDIM], g_vin_l[MTOT * EDIM];
__device__ bf16 g_qw_h[EDIM * EDIM], g_qw_l[EDIM * EDIM];
__device__ bf16 g_kw_h[EDIM * EDIM], g_kw_l[EDIM * EDIM];
__device__ bf16 g_vw_h[EDIM * EDIM], g_vw_l[EDIM * EDIM];
__device__ bf16 g_ow_h[EDIM * EDIM], g_ow_l[EDIM * EDIM];
__device__ bf16 g_Qh[MTOT * EDIM], g_Ql[MTOT * EDIM];
__device__ bf16 g_Kh[MTOT * EDIM], g_Kl[MTOT * EDIM];
__device__ bf16 g_VTh[(long long)EDIM * MTOT], g_VTl[(long long)EDIM * MTOT];
__device__ float g_S[(long long)BATCH * SDIM * SDIM];
__device__ bf16 g_Ph[(long long)BATCH * SDIM * SDIM];
__device__ bf16 g_Pl[(long long)BATCH * SDIM * SDIM];
__device__ bf16 g_Oh[MTOT * EDIM], g_Ol[MTOT * EDIM];

// ---------------------------------------------------------------------------
// fp32 -> bf16 hi/lo split (vectorized by 4)
// ---------------------------------------------------------------------------
__global__ void cvt_hilo_kernel(const float* __restrict__ x,
                                bf16* __restrict__ h, bf16* __restrict__ l,
                                long long n4) {
    long long i = (long long)blockIdx.x * blockDim.x + threadIdx.x;
    if (i >= n4) return;
    float4 v = reinterpret_cast<const float4*>(x)[i];
    bf16 h0 = __float2bfloat16(v.x), h1 = __float2bfloat16(v.y);
    bf16 h2 = __float2bfloat16(v.z), h3 = __float2bfloat16(v.w);
    bf16 l0 = __float2bfloat16(v.x - __bfloat162float(h0));
    bf16 l1 = __float2bfloat16(v.y - __bfloat162float(h1));
    bf16 l2 = __float2bfloat16(v.z - __bfloat162float(h2));
    bf16 l3 = __float2bfloat16(v.w - __bfloat162float(h3));
    reinterpret_cast<__nv_bfloat162*>(h)[i * 2 + 0] = __nv_bfloat162(h0, h1);
    reinterpret_cast<__nv_bfloat162*>(h)[i * 2 + 1] = __nv_bfloat162(h2, h3);
    reinterpret_cast<__nv_bfloat162*>(l)[i * 2 + 0] = __nv_bfloat162(l0, l1);
    reinterpret_cast<__nv_bfloat162*>(l)[i * 2 + 1] = __nv_bfloat162(l2, l3);
}

// ---------------------------------------------------------------------------
// Rank-16 projection: XA[m][r] = sum_e X[m][e] * Aw[r][e].  One warp per row.
// ---------------------------------------------------------------------------
__global__ void lora_xa_kernel(const float* __restrict__ X,
                               const float* __restrict__ Aw,
                               float* __restrict__ XA, int K) {
    int warp = (blockIdx.x * blockDim.x + threadIdx.x) >> 5;
    int lane = threadIdx.x & 31;
    const float* x = X + (long long)warp * K;
    float acc[16];
#pragma unroll
    for (int r = 0; r < 16; r++) acc[r] = 0.f;
    for (int e = lane; e < K; e += 32) {
        float xv = x[e];
#pragma unroll
        for (int r = 0; r < 16; r++) acc[r] += xv * Aw[r * K + e];
    }
#pragma unroll
    for (int r = 0; r < 16; r++) {
#pragma unroll
        for (int off = 16; off; off >>= 1)
            acc[r] += __shfl_xor_sync(0xFFFFFFFFu, acc[r], off);
    }
    if (lane == 0) {
#pragma unroll
        for (int r = 0; r < 16; r++) XA[(long long)warp * 16 + r] = acc[r];
    }
}

// ---------------------------------------------------------------------------
// split-bf16 HMMA GEMM.  D[m][n] = sum_k A[m][k]*B[n][k] (NT, K-major rows),
// computed as Ahi*Bhi + Ahi*Blo + Alo*Bhi, fp32 accumulate in registers.
// CTA tile 128x128, K-chunk 32, double-buffered cp.async smem.
// 8 warps as 2(m) x 4(n); each warp 64x32 via m16n8k16 fragments.
// Epilogue variants:
//   EPI 0: outF[z*sC + m*ldOut + n] = alpha*acc
//   EPI 1: d = acc + loraX[m]·loraW[n]; hi/lo -> outH/outL[m*ldOut + n]
//   EPI 2: same but transposed store [n*ldOut + m]
//   EPI 3: hi/lo -> outH/outL[z*sC + m*ldOut + n]
// ---------------------------------------------------------------------------
template <int EPI>
__global__ void __launch_bounds__(256, 1)
mma_gemm(const bf16* __restrict__ Ah_, const bf16* __restrict__ Al_,
         const bf16* __restrict__ Bh_, const bf16* __restrict__ Bl_,
         int K, int lda, int ldb,
         long long sA, long long sB, long long sC,
         float alpha,
         float* __restrict__ outF,
         bf16* __restrict__ outH, bf16* __restrict__ outL, int ldOut,
         const float* __restrict__ loraX, const float* __restrict__ loraW) {
    extern __shared__ char smem[];

    const int tid = threadIdx.x;
    const int wid = tid >> 5;
    const int lane = tid & 31;
    const int g = lane >> 2;     // group id 0..7
    const int tg = lane & 3;     // thread in group
    const int warp_m = wid >> 2; // 0..1
    const int warp_n = wid & 3;  // 0..3
    const int m0 = blockIdx.y * 128;
    const int n0 = blockIdx.x * 128;
    const long long z = blockIdx.z;

    const bf16* pAh = Ah_ + z * sA + (long long)m0 * lda;
    const bf16* pAl = Al_ + z * sA + (long long)m0 * lda;
    const bf16* pBh = Bh_ + z * sB + (long long)n0 * ldb;
    const bf16* pBl = Bl_ + z * sB + (long long)n0 * ldb;

    float acc[4][4][4];
#pragma unroll
    for (int mi = 0; mi < 4; mi++)
#pragma unroll
        for (int ni = 0; ni < 4; ni++)
#pragma unroll
            for (int r = 0; r < 4; r++) acc[mi][ni][r] = 0.f;

    const int NC = K / KC;

    auto fill = [&](int stg, int c) {
        const int k0 = c * KC;
        char* sb = smem + stg * STAGE_B;
#pragma unroll
        for (int i = 0; i < 8; i++) {
            int idx = tid + i * 256;       // 0..2047
            int tile = idx >> 9;           // 0..3
            int rem = idx & 511;
            int row = rem >> 2;            // 0..127
            int ch = rem & 3;              // 16B chunk
            const bf16* src;
            if (tile == 0)      src = pAh + (long long)row * lda + k0 + ch * 8;
            else if (tile == 1) src = pAl + (long long)row * lda + k0 + ch * 8;
            else if (tile == 2) src = pBh + (long long)row * ldb + k0 + ch * 8;
            else                src = pBl + (long long)row * ldb + k0 + ch * 8;
            cp_async16(smem_u32(sb + tile * TILE_B + row * ROWB + ch * 16), src);
        }
        asm volatile("cp.async.commit_group;" ::: "memory");
    };

    fill(0, 0);
    for (int c = 0; c < NC; c++) {
        if (c + 1 < NC) {
            fill((c + 1) & 1, c + 1);
            asm volatile("cp.async.wait_group 1;" ::: "memory");
        } else {
            asm volatile("cp.async.wait_group 0;" ::: "memory");
        }
        __syncthreads();

        const char* sb = smem + (c & 1) * STAGE_B;
#pragma unroll
        for (int ks = 0; ks < 2; ks++) {
            uint32_t ah[4][4], al[4][4], bh[4][2], bl[4][2];
#pragma unroll
            for (int mi = 0; mi < 4; mi++) {
                int row = warp_m * 64 + mi * 16 + g;
                const char* bh_ = sb;              // Ahi tile
                const char* bl_ = sb + TILE_B;     // Alo tile
                int o0 = row * ROWB + ks * 32 + tg * 4;
                int o1 = (row + 8) * ROWB + ks * 32 + tg * 4;
                ah[mi][0] = *(const uint32_t*)(bh_ + o0);
                ah[mi][1] = *(const uint32_t*)(bh_ + o1);
                ah[mi][2] = *(const uint32_t*)(bh_ + o0 + 16);
                ah[mi][3] = *(const uint32_t*)(bh_ + o1 + 16);
                al[mi][0] = *(const uint32_t*)(bl_ + o0);
                al[mi][1] = *(const uint32_t*)(bl_ + o1);
                al[mi][2] = *(const uint32_t*)(bl_ + o0 + 16);
                al[mi][3] = *(const uint32_t*)(bl_ + o1 + 16);
            }
#pragma unroll
            for (int ni = 0; ni < 4; ni++) {
                int row = warp_n * 32 + ni * 8 + g;
                const char* bh_ = sb + 2 * TILE_B; // Bhi tile
                const char* bl_ = sb + 3 * TILE_B; // Blo tile
                int o0 = row * ROWB + ks * 32 + tg * 4;
                bh[ni][0] = *(const uint32_t*)(bh_ + o0);
                bh[ni][1] = *(const uint32_t*)(bh_ + o0 + 16);
                bl[ni][0] = *(const uint32_t*)(bl_ + o0);
                bl[ni][1] = *(const uint32_t*)(bl_ + o0 + 16);
            }
#pragma unroll
            for (int mi = 0; mi < 4; mi++)
#pragma unroll
                for (int ni = 0; ni < 4; ni++) {
                    mma_bf16(acc[mi][ni], ah[mi], bh[ni]);
                    mma_bf16(acc[mi][ni], ah[mi], bl[ni]);
                    mma_bf16(acc[mi][ni], al[mi], bh[ni]);
                }
        }
        __syncthreads();
    }

    // ---- LoRA staging into smem (EPI 1/2 only) ----
    float* sx = (float*)smem;                    // [128][20]
    float* sw = (float*)(smem + 128 * 20 * 4);   // [128][20]
    if (EPI == 1 || EPI == 2) {
        for (int i = tid; i < 128 * 16; i += 256) {
            int r = i >> 4, t = i & 15;
            sx[r * 20 + t] = loraX[(long long)(m0 + r) * 16 + t];
            sw[r * 20 + t] = loraW[(long long)(n0 + r) * 16 + t];
        }
        __syncthreads();
    }

    // ---- epilogue ----
#pragma unroll
    for (int mi = 0; mi < 4; mi++) {
#pragma unroll
        for (int rr = 0; rr < 2; rr++) {
            int mlocal = warp_m * 64 + mi * 16 + g + rr * 8;
            int m = m0 + mlocal;
            float xa[16];
            if (EPI == 1 || EPI == 2) {
#pragma unroll
                for (int t = 0; t < 16; t++) xa[t] = sx[mlocal * 20 + t];
            }
#pragma unroll
            for (int ni = 0; ni < 4; ni++) {
                float v0 = acc[mi][ni][rr * 2 + 0];
                float v1 = acc[mi][ni][rr * 2 + 1];
                int nlocal = warp_n * 32 + ni * 8 + tg * 2;
                int n = n0 + nlocal;
                if (EPI == 0) {
                    long long base = z * sC + (long long)m * ldOut + n;
                    outF[base] = alpha * v0;
                    outF[base + 1] = alpha * v1;
                } else if (EPI == 1 || EPI == 2) {
                    float d0 = v0, d1 = v1;
#pragma unroll
                    for (int t = 0; t < 16; t++) {
                        d0 += xa[t] * sw[nlocal * 20 + t];
                        d1 += xa[t] * sw[(nlocal + 1) * 20 + t];
                    }
                    bf16 h0 = __float2bfloat16(d0);
                    bf16 l0 = __float2bfloat16(d0 - __bfloat162float(h0));
                    bf16 h1 = __float2bfloat16(d1);
                    bf16 l1 = __float2bfloat16(d1 - __bfloat162float(h1));
                    if (EPI == 1) {
                        long long i0 = (long long)m * ldOut + n;
                        outH[i0] = h0; outH[i0 + 1] = h1;
                        outL[i0] = l0; outL[i0 + 1] = l1;
                    } else {
                        long long i0 = (long long)n * ldOut + m;
                        long long i1 = (long long)(n + 1) * ldOut + m;
                        outH[i0] = h0; outH[i1] = h1;
                        outL[i0] = l0; outL[i1] = l1;
                    }
                } else {  // EPI 3
                    long long i0 = z * sC + (long long)m * ldOut + n;
                    bf16 h0 = __float2bfloat16(v0);
                    bf16 h1 = __float2bfloat16(v1);
                    outH[i0] = h0;
                    outH[i0 + 1] = h1;
                    outL[i0] = __float2bfloat16(v0 - __bfloat162float(h0));
                    outL[i0 + 1] = __float2bfloat16(v1 - __bfloat162float(h1));
                }
            }
        }
    }
}

// ---------------------------------------------------------------------------
// Row softmax over 2048 cols; writes bf16 hi/lo probability arrays.
// ---------------------------------------------------------------------------
__global__ void softmax_rows_kernel(const float* __restrict__ S,
                                    bf16* __restrict__ Ph,
                                    bf16* __restrict__ Pl) {
    const int NCOL = SDIM;
    const int VPT = 8;
    const float* row = S + (long long)blockIdx.x * NCOL;
    bf16* rh = Ph + (long long)blockIdx.x * NCOL;
    bf16* rl = Pl + (long long)blockIdx.x * NCOL;
    int tid = threadIdx.x;

    float v[VPT];
    float mx = -INFINITY;
#pragma unroll
    for (int i = 0; i < VPT; i++) {
        v[i] = row[tid + i * 256];
        mx = fmaxf(mx, v[i]);
    }
    __shared__ float red[256];
    red[tid] = mx;
    __syncthreads();
#pragma unroll
    for (int s = 128; s > 0; s >>= 1) {
        if (tid < s) red[tid] = fmaxf(red[tid], red[tid + s]);
        __syncthreads();
    }
    mx = red[0];
    __syncthreads();
    float sum = 0.f;
#pragma unroll
    for (int i = 0; i < VPT; i++) {
        v[i] = __expf(v[i] - mx);
        sum += v[i];
    }
    red[tid] = sum;
    __syncthreads();
#pragma unroll
    for (int s = 128; s > 0; s >>= 1) {
        if (tid < s) red[tid] += red[tid + s];
        __syncthreads();
    }
    float inv = 1.f / red[0];
#pragma unroll
    for (int i = 0; i < VPT; i++) {
        float p = v[i] * inv;
        bf16 hh = __float2bfloat16(p);
        rh[tid + i * 256] = hh;
        rl[tid + i * 256] = __float2bfloat16(p - __bfloat162float(hh));
    }
}

// ---------------------------------------------------------------------------
// Launch
// ---------------------------------------------------------------------------
extern "C" void kernel_launch(void* const* d_in, const int* in_sizes, int n_in,
                              void* d_out, int out_size) {
    const float* query = (const float*)d_in[0];
    const float* key_ = (const float*)d_in[1];
    const float* value = (const float*)d_in[2];
    const float* Qw = (const float*)d_in[3];
    const float* Kw = (const float*)d_in[4];
    const float* Vw = (const float*)d_in[5];
    const float* QA = (const float*)d_in[6];
    const float* QB = (const float*)d_in[7];
    const float* KA = (const float*)d_in[8];
    const float* KB = (const float*)d_in[9];
    const float* VA = (const float*)d_in[10];
    const float* VB = (const float*)d_in[11];
    const float* Ow = (const float*)d_in[12];
    float* out = (float*)d_out;

    cudaFuncSetAttribute(mma_gemm<0>, cudaFuncAttributeMaxDynamicSharedMemorySize, SMEM_DYN);
    cudaFuncSetAttribute(mma_gemm<1>, cudaFuncAttributeMaxDynamicSharedMemorySize, SMEM_DYN);
    cudaFuncSetAttribute(mma_gemm<2>, cudaFuncAttributeMaxDynamicSharedMemorySize, SMEM_DYN);
    cudaFuncSetAttribute(mma_gemm<3>, cudaFuncAttributeMaxDynamicSharedMemorySize, SMEM_DYN);

    float *pXAq, *pXAk, *pXAv, *pS;
    bf16 *qin_h, *qin_l, *kin_h, *kin_l, *vin_h, *vin_l;
    bf16 *qw_h, *qw_l, *kw_h, *kw_l, *vw_h, *vw_l, *ow_h, *ow_l;
    bf16 *Qh, *Ql, *Kh, *Kl, *VTh, *VTl, *Phh, *Pll, *Ohh, *Oll;
    cudaGetSymbolAddress((void**)&pXAq, g_XAq);
    cudaGetSymbolAddress((void**)&pXAk, g_XAk);
    cudaGetSymbolAddress((void**)&pXAv, g_XAv);
    cudaGetSymbolAddress((void**)&pS, g_S);
    cudaGetSymbolAddress((void**)&qin_h, g_qin_h);
    cudaGetSymbolAddress((void**)&qin_l, g_qin_l);
    cudaGetSymbolAddress((void**)&kin_h, g_kin_h);
    cudaGetSymbolAddress((void**)&kin_l, g_kin_l);
    cudaGetSymbolAddress((void**)&vin_h, g_vin_h);
    cudaGetSymbolAddress((void**)&vin_l, g_vin_l);
    cudaGetSymbolAddress((void**)&qw_h, g_qw_h);
    cudaGetSymbolAddress((void**)&qw_l, g_qw_l);
    cudaGetSymbolAddress((void**)&kw_h, g_kw_h);
    cudaGetSymbolAddress((void**)&kw_l, g_kw_l);
    cudaGetSymbolAddress((void**)&vw_h, g_vw_h);
    cudaGetSymbolAddress((void**)&vw_l, g_vw_l);
    cudaGetSymbolAddress((void**)&ow_h, g_ow_h);
    cudaGetSymbolAddress((void**)&ow_l, g_ow_l);
    cudaGetSymbolAddress((void**)&Qh, g_Qh);
    cudaGetSymbolAddress((void**)&Ql, g_Ql);
    cudaGetSymbolAddress((void**)&Kh, g_Kh);
    cudaGetSymbolAddress((void**)&Kl, g_Kl);
    cudaGetSymbolAddress((void**)&VTh, g_VTh);
    cudaGetSymbolAddress((void**)&VTl, g_VTl);
    cudaGetSymbolAddress((void**)&Phh, g_Ph);
    cudaGetSymbolAddress((void**)&Pll, g_Pl);
    cudaGetSymbolAddress((void**)&Ohh, g_Oh);
    cudaGetSymbolAddress((void**)&Oll, g_Ol);

    const long long nin4 = (long long)MTOT * EDIM / 4;
    const long long nw4 = (long long)EDIM * EDIM / 4;
    cvt_hilo_kernel<<<(int)(nin4 / 256), 256>>>(query, qin_h, qin_l, nin4);
    cvt_hilo_kernel<<<(int)(nin4 / 256), 256>>>(key_, kin_h, kin_l, nin4);
    cvt_hilo_kernel<<<(int)(nin4 / 256), 256>>>(value, vin_h, vin_l, nin4);
    cvt_hilo_kernel<<<(int)(nw4 / 256), 256>>>(Qw, qw_h, qw_l, nw4);
    cvt_hilo_kernel<<<(int)(nw4 / 256), 256>>>(Kw, kw_h, kw_l, nw4);
    cvt_hilo_kernel<<<(int)(nw4 / 256), 256>>>(Vw, vw_h, vw_l, nw4);
    cvt_hilo_kernel<<<(int)(nw4 / 256), 256>>>(Ow, ow_h, ow_l, nw4);

    lora_xa_kernel<<<MTOT / 8, 256>>>(query, QA, pXAq, EDIM);
    lora_xa_kernel<<<MTOT / 8, 256>>>(key_, KA, pXAk, EDIM);
    lora_xa_kernel<<<MTOT / 8, 256>>>(value, VA, pXAv, EDIM);

    // Q/K/V projections: M=8192, N=1024, K=1024 (NT), LoRA fused
    dim3 gproj(EDIM / 128, MTOT / 128, 1);
    mma_gemm<1><<<gproj, 256, SMEM_DYN>>>(qin_h, qin_l, qw_h, qw_l,
                                          EDIM, EDIM, EDIM, 0, 0, 0, 1.f,
                                          nullptr, Qh, Ql, EDIM, pXAq, QB);
    mma_gemm<1><<<gproj, 256, SMEM_DYN>>>(kin_h, kin_l, kw_h, kw_l,
                                          EDIM, EDIM, EDIM, 0, 0, 0, 1.f,
                                          nullptr, Kh, Kl, EDIM, pXAk, KB);
    mma_gemm<2><<<gproj, 256, SMEM_DYN>>>(vin_h, vin_l, vw_h, vw_l,
                                          EDIM, EDIM, EDIM, 0, 0, 0, 1.f,
                                          nullptr, VTh, VTl, MTOT, pXAv, VB);

    // scores = Q K^T / 32 : batched, M=N=2048, K=1024
    dim3 gsc(SDIM / 128, SDIM / 128, BATCH);
    mma_gemm<0><<<gsc, 256, SMEM_DYN>>>(Qh, Ql, Kh, Kl,
                                        EDIM, EDIM, EDIM,
                                        (long long)SDIM * EDIM,
                                        (long long)SDIM * EDIM,
                                        (long long)SDIM * SDIM,
                                        1.f / 32.f, pS, nullptr, nullptr, SDIM,
                                        nullptr, nullptr);

    softmax_rows_kernel<<<BATCH * SDIM, 256>>>(pS, Phh, Pll);

    // out = attn @ V : A=P [2048x2048], B=VT [1024 x 8192], K=2048
    dim3 gav(EDIM / 128, SDIM / 128, BATCH);
    mma_gemm<3><<<gav, 256, SMEM_DYN>>>(Phh, Pll, VTh, VTl,
                                        SDIM, SDIM, MTOT,
                                        (long long)SDIM * SDIM,
                                        (long long)SDIM,
                                        (long long)SDIM * EDIM,
                                        1.f, nullptr, Ohh, Oll, EDIM,
                                        nullptr, nullptr);

    // final = out @ O^T -> d_out (fp32)
    mma_gemm<0><<<gproj, 256, SMEM_DYN>>>(Ohh, Oll, ow_h, ow_l,
                                          EDIM, EDIM, EDIM, 0, 0, 0, 1.f,
                                          out, nullptr, nullptr, EDIM,
                                          nullptr, nullptr);
}

// round 17
// speedup vs baseline: 2.5056x; 1.0209x over previous
#include <cuda_runtime.h>
#include <cuda_bf16.h>
#include <math.h>
#include <stdint.h>

// ============================================================================
// LoRA attention via mma.sync (HMMA) split-bf16 3-pass GEMMs + ldmatrix.
// Base sm_103 target compatible: NO tcgen05 (toolchain lowers at sm_103).
// B=4, S=2048, E=1024, R=16.  M = B*S = 8192.
// ============================================================================

#define EDIM 1024
#define SDIM 2048
#define BATCH 4
#define MTOT 8192
#define KC 32                    // K elements per chunk
#define ROWB 80                  // padded row stride bytes (32 bf16 = 64B + 16B pad)
#define TILE_B (128 * ROWB)      // 10240 B per 128x32 tile
#define STAGE_B (4 * TILE_B)     // Ahi, Alo, Bhi, Blo = 40960 B
#define SMEM_DYN (2 * STAGE_B)   // 81920 B

typedef __nv_bfloat16 bf16;

static __device__ __forceinline__ uint32_t smem_u32(const void* p) {
    uint32_t a;
    asm("{ .reg .u64 t; cvta.to.shared.u64 t, %1; cvt.u32.u64 %0, t; }"
        : "=r"(a) : "l"(p));
    return a;
}

static __device__ __forceinline__ void cp_async16(uint32_t dst, const void* src) {
    asm volatile("cp.async.cg.shared.global [%0], [%1], 16;"
                 :: "r"(dst), "l"(src) : "memory");
}

static __device__ __forceinline__ void mma_bf16(float* c, const uint32_t* a,
                                                const uint32_t* b) {
    asm volatile(
        "mma.sync.aligned.m16n8k16.row.col.f32.bf16.bf16.f32 "
        "{%0,%1,%2,%3}, {%4,%5,%6,%7}, {%8,%9}, {%0,%1,%2,%3};"
        : "+f"(c[0]), "+f"(c[1]), "+f"(c[2]), "+f"(c[3])
        : "r"(a[0]), "r"(a[1]), "r"(a[2]), "r"(a[3]), "r"(b[0]), "r"(b[1]));
}

static __device__ __forceinline__ void ldsm_x4(uint32_t* r, uint32_t addr) {
    asm volatile("ldmatrix.sync.aligned.m8n8.x4.shared.b16 {%0,%1,%2,%3}, [%4];"
                 : "=r"(r[0]), "=r"(r[1]), "=r"(r[2]), "=r"(r[3]) : "r"(addr));
}

static __device__ __forceinline__ void ldsm_x2(uint32_t* r, uint32_t addr) {
    asm volatile("ldmatrix.sync.aligned.m8n8.x2.shared.b16 {%0,%1}, [%2];"
                 : "=r"(r[0]), "=r"(r[1]) : "r"(addr));
}

// ---------------------------------------------------------------------------
// Scratch (device globals; no allocations allowed).
// ---------------------------------------------------------------------------
__device__ float g_XAq[MTOT * 16];
__device__ float g_XAk[MTOT * 16];
__device__ float g_XAv[MTOT * 16];
__device__ bf16 g_qin_h[MTOT * EDIM], g_qin_l[MTOT * EDIM];
__device__ bf16 g_kin_h[MTOT * EDIM], g_kin_l[MTOT * EDIM];
__device__ bf16 g_vin_h[MTOT * EDIM], g_vin_l[MTOT * EDIM];
__device__ bf16 g_qw_h[EDIM * EDIM], g_qw_l[EDIM * EDIM];
__device__ bf16 g_kw_h[EDIM * EDIM], g_kw_l[EDIM * EDIM];
__device__ bf16 g_vw_h[EDIM * EDIM], g_vw_l[EDIM * EDIM];
__device__ bf16 g_ow_h[EDIM * EDIM], g_ow_l[EDIM * EDIM];
__device__ bf16 g_Qh[MTOT * EDIM], g_Ql[MTOT * EDIM];
__device__ bf16 g_Kh[MTOT * EDIM], g_Kl[MTOT * EDIM];
__device__ bf16 g_VTh[(long long)EDIM * MTOT], g_VTl[(long long)EDIM * MTOT];
__device__ float g_S[(long long)BATCH * SDIM * SDIM];
__device__ bf16 g_Ph[(long long)BATCH * SDIM * SDIM];
__device__ bf16 g_Pl[(long long)BATCH * SDIM * SDIM];
__device__ bf16 g_Oh[MTOT * EDIM], g_Ol[MTOT * EDIM];

// ---------------------------------------------------------------------------
// fp32 -> bf16 hi/lo split (vectorized by 4)
// ---------------------------------------------------------------------------
__global__ void cvt_hilo_kernel(const float* __restrict__ x,
                                bf16* __restrict__ h, bf16* __restrict__ l,
                                long long n4) {
    long long i = (long long)blockIdx.x * blockDim.x + threadIdx.x;
    if (i >= n4) return;
    float4 v = reinterpret_cast<const float4*>(x)[i];
    bf16 h0 = __float2bfloat16(v.x), h1 = __float2bfloat16(v.y);
    bf16 h2 = __float2bfloat16(v.z), h3 = __float2bfloat16(v.w);
    bf16 l0 = __float2bfloat16(v.x - __bfloat162float(h0));
    bf16 l1 = __float2bfloat16(v.y - __bfloat162float(h1));
    bf16 l2 = __float2bfloat16(v.z - __bfloat162float(h2));
    bf16 l3 = __float2bfloat16(v.w - __bfloat162float(h3));
    reinterpret_cast<__nv_bfloat162*>(h)[i * 2 + 0] = __nv_bfloat162(h0, h1);
    reinterpret_cast<__nv_bfloat162*>(h)[i * 2 + 1] = __nv_bfloat162(h2, h3);
    reinterpret_cast<__nv_bfloat162*>(l)[i * 2 + 0] = __nv_bfloat162(l0, l1);
    reinterpret_cast<__nv_bfloat162*>(l)[i * 2 + 1] = __nv_bfloat162(l2, l3);
}

// ---------------------------------------------------------------------------
// Rank-16 projection: XA[m][r] = sum_e X[m][e] * Aw[r][e].  One warp per row.
// ---------------------------------------------------------------------------
__global__ void lora_xa_kernel(const float* __restrict__ X,
                               const float* __restrict__ Aw,
                               float* __restrict__ XA, int K) {
    int warp = (blockIdx.x * blockDim.x + threadIdx.x) >> 5;
    int lane = threadIdx.x & 31;
    const float* x = X + (long long)warp * K;
    float acc[16];
#pragma unroll
    for (int r = 0; r < 16; r++) acc[r] = 0.f;
    for (int e = lane; e < K; e += 32) {
        float xv = x[e];
#pragma unroll
        for (int r = 0; r < 16; r++) acc[r] += xv * Aw[r * K + e];
    }
#pragma unroll
    for (int r = 0; r < 16; r++) {
#pragma unroll
        for (int off = 16; off; off >>= 1)
            acc[r] += __shfl_xor_sync(0xFFFFFFFFu, acc[r], off);
    }
    if (lane == 0) {
#pragma unroll
        for (int r = 0; r < 16; r++) XA[(long long)warp * 16 + r] = acc[r];
    }
}

// ---------------------------------------------------------------------------
// split-bf16 HMMA GEMM.  D[m][n] = sum_k A[m][k]*B[n][k] (NT, K-major rows),
// computed as Ahi*Bhi + Ahi*Blo + Alo*Bhi, fp32 accumulate in registers.
// CTA tile 128x128, K-chunk 32, double-buffered cp.async smem, ldmatrix loads.
// 8 warps as 2(m) x 4(n); each warp 64x32 via m16n8k16 fragments.
// Epilogue variants:
//   EPI 0: outF[z*sC + m*ldOut + n] = alpha*acc
//   EPI 1: d = acc + loraX[m]·loraW[n]; hi/lo -> outH/outL[m*ldOut + n]
//   EPI 2: same but transposed store [n*ldOut + m]
//   EPI 3: hi/lo -> outH/outL[z*sC + m*ldOut + n]
// ---------------------------------------------------------------------------
template <int EPI>
__global__ void __launch_bounds__(256, 1)
mma_gemm(const bf16* __restrict__ Ah_, const bf16* __restrict__ Al_,
         const bf16* __restrict__ Bh_, const bf16* __restrict__ Bl_,
         int K, int lda, int ldb,
         long long sA, long long sB, long long sC,
         float alpha,
         float* __restrict__ outF,
         bf16* __restrict__ outH, bf16* __restrict__ outL, int ldOut,
         const float* __restrict__ loraX, const float* __restrict__ loraW) {
    extern __shared__ char smem[];

    const int tid = threadIdx.x;
    const int wid = tid >> 5;
    const int lane = tid & 31;
    const int g = lane >> 2;     // group id 0..7
    const int tg = lane & 3;     // thread in group
    const int warp_m = wid >> 2; // 0..1
    const int warp_n = wid & 3;  // 0..3
    const int m0 = blockIdx.y * 128;
    const int n0 = blockIdx.x * 128;
    const long long z = blockIdx.z;

    const bf16* pAh = Ah_ + z * sA + (long long)m0 * lda;
    const bf16* pAl = Al_ + z * sA + (long long)m0 * lda;
    const bf16* pBh = Bh_ + z * sB + (long long)n0 * ldb;
    const bf16* pBl = Bl_ + z * sB + (long long)n0 * ldb;

    const uint32_t sbase = smem_u32(smem);
    // per-lane ldmatrix address components (constant across chunks)
    const uint32_t a_lane_off =
        (uint32_t)((warp_m * 64 + (lane & 15)) * ROWB + (lane >> 4) * 16);
    const uint32_t b_lane_off =
        (uint32_t)((warp_n * 32 + (lane & 7)) * ROWB + ((lane >> 3) & 1) * 16);

    float acc[4][4][4];
#pragma unroll
    for (int mi = 0; mi < 4; mi++)
#pragma unroll
        for (int ni = 0; ni < 4; ni++)
#pragma unroll
            for (int r = 0; r < 4; r++) acc[mi][ni][r] = 0.f;

    const int NC = K / KC;

    auto fill = [&](int stg, int c) {
        const int k0 = c * KC;
        char* sb = smem + stg * STAGE_B;
#pragma unroll
        for (int i = 0; i < 8; i++) {
            int idx = tid + i * 256;       // 0..2047
            int tile = idx >> 9;           // 0..3
            int rem = idx & 511;
            int row = rem >> 2;            // 0..127
            int ch = rem & 3;              // 16B chunk
            const bf16* src;
            if (tile == 0)      src = pAh + (long long)row * lda + k0 + ch * 8;
            else if (tile == 1) src = pAl + (long long)row * lda + k0 + ch * 8;
            else if (tile == 2) src = pBh + (long long)row * ldb + k0 + ch * 8;
            else                src = pBl + (long long)row * ldb + k0 + ch * 8;
            cp_async16(smem_u32(sb + tile * TILE_B + row * ROWB + ch * 16), src);
        }
        asm volatile("cp.async.commit_group;" ::: "memory");
    };

    fill(0, 0);
    for (int c = 0; c < NC; c++) {
        if (c + 1 < NC) {
            fill((c + 1) & 1, c + 1);
            asm volatile("cp.async.wait_group 1;" ::: "memory");
        } else {
            asm volatile("cp.async.wait_group 0;" ::: "memory");
        }
        __syncthreads();

        const uint32_t sb32 = sbase + (uint32_t)((c & 1) * STAGE_B);
#pragma unroll
        for (int ks = 0; ks < 2; ks++) {
            uint32_t ah[4][4], al[4][4], bh[4][2], bl[4][2];
            const uint32_t kso = (uint32_t)(ks * 32);
#pragma unroll
            for (int mi = 0; mi < 4; mi++) {
                uint32_t ao = sb32 + a_lane_off + kso + (uint32_t)(mi * 16 * ROWB);
                ldsm_x4(ah[mi], ao);
                ldsm_x4(al[mi], ao + TILE_B);
            }
#pragma unroll
            for (int ni = 0; ni < 4; ni++) {
                uint32_t bo = sb32 + 2 * TILE_B + b_lane_off + kso +
                              (uint32_t)(ni * 8 * ROWB);
                ldsm_x2(bh[ni], bo);
                ldsm_x2(bl[ni], bo + TILE_B);
            }
#pragma unroll
            for (int mi = 0; mi < 4; mi++)
#pragma unroll
                for (int ni = 0; ni < 4; ni++) {
                    mma_bf16(acc[mi][ni], ah[mi], bh[ni]);
                    mma_bf16(acc[mi][ni], ah[mi], bl[ni]);
                    mma_bf16(acc[mi][ni], al[mi], bh[ni]);
                }
        }
        __syncthreads();
    }

    // ---- LoRA staging into smem (EPI 1/2 only) ----
    float* sx = (float*)smem;                    // [128][20]
    float* sw = (float*)(smem + 128 * 20 * 4);   // [128][20]
    if (EPI == 1 || EPI == 2) {
        for (int i = tid; i < 128 * 16; i += 256) {
            int r = i >> 4, t = i & 15;
            sx[r * 20 + t] = loraX[(long long)(m0 + r) * 16 + t];
            sw[r * 20 + t] = loraW[(long long)(n0 + r) * 16 + t];
        }
        __syncthreads();
    }

    // ---- epilogue ----
#pragma unroll
    for (int mi = 0; mi < 4; mi++) {
#pragma unroll
        for (int rr = 0; rr < 2; rr++) {
            int mlocal = warp_m * 64 + mi * 16 + g + rr * 8;
            int m = m0 + mlocal;
            float xa[16];
            if (EPI == 1 || EPI == 2) {
#pragma unroll
                for (int t = 0; t < 16; t++) xa[t] = sx[mlocal * 20 + t];
            }
#pragma unroll
            for (int ni = 0; ni < 4; ni++) {
                float v0 = acc[mi][ni][rr * 2 + 0];
                float v1 = acc[mi][ni][rr * 2 + 1];
                int nlocal = warp_n * 32 + ni * 8 + tg * 2;
                int n = n0 + nlocal;
                if (EPI == 0) {
                    long long base = z * sC + (long long)m * ldOut + n;
                    outF[base] = alpha * v0;
                    outF[base + 1] = alpha * v1;
                } else if (EPI == 1 || EPI == 2) {
                    float d0 = v0, d1 = v1;
#pragma unroll
                    for (int t = 0; t < 16; t++) {
                        d0 += xa[t] * sw[nlocal * 20 + t];
                        d1 += xa[t] * sw[(nlocal + 1) * 20 + t];
                    }
                    bf16 h0 = __float2bfloat16(d0);
                    bf16 l0 = __float2bfloat16(d0 - __bfloat162float(h0));
                    bf16 h1 = __float2bfloat16(d1);
                    bf16 l1 = __float2bfloat16(d1 - __bfloat162float(h1));
                    if (EPI == 1) {
                        long long i0 = (long long)m * ldOut + n;
                        outH[i0] = h0; outH[i0 + 1] = h1;
                        outL[i0] = l0; outL[i0 + 1] = l1;
                    } else {
                        long long i0 = (long long)n * ldOut + m;
                        long long i1 = (long long)(n + 1) * ldOut + m;
                        outH[i0] = h0; outH[i1] = h1;
                        outL[i0] = l0; outL[i1] = l1;
                    }
                } else {  // EPI 3
                    long long i0 = z * sC + (long long)m * ldOut + n;
                    bf16 h0 = __float2bfloat16(v0);
                    bf16 h1 = __float2bfloat16(v1);
                    outH[i0] = h0;
                    outH[i0 + 1] = h1;
                    outL[i0] = __float2bfloat16(v0 - __bfloat162float(h0));
                    outL[i0 + 1] = __float2bfloat16(v1 - __bfloat162float(h1));
                }
            }
        }
    }
}

// ---------------------------------------------------------------------------
// Row softmax over 2048 cols; writes bf16 hi/lo probability arrays.
// ---------------------------------------------------------------------------
__global__ void softmax_rows_kernel(const float* __restrict__ S,
                                    bf16* __restrict__ Ph,
                                    bf16* __restrict__ Pl) {
    const int NCOL = SDIM;
    const int VPT = 8;
    const float* row = S + (long long)blockIdx.x * NCOL;
    bf16* rh = Ph + (long long)blockIdx.x * NCOL;
    bf16* rl = Pl + (long long)blockIdx.x * NCOL;
    int tid = threadIdx.x;

    float v[VPT];
    float mx = -INFINITY;
#pragma unroll
    for (int i = 0; i < VPT; i++) {
        v[i] = row[tid + i * 256];
        mx = fmaxf(mx, v[i]);
    }
    __shared__ float red[256];
    red[tid] = mx;
    __syncthreads();
#pragma unroll
    for (int s = 128; s > 0; s >>= 1) {
        if (tid < s) red[tid] = fmaxf(red[tid], red[tid + s]);
        __syncthreads();
    }
    mx = red[0];
    __syncthreads();
    float sum = 0.f;
#pragma unroll
    for (int i = 0; i < VPT; i++) {
        v[i] = __expf(v[i] - mx);
        sum += v[i];
    }
    red[tid] = sum;
    __syncthreads();
#pragma unroll
    for (int s = 128; s > 0; s >>= 1) {
        if (tid < s) red[tid] += red[tid + s];
        __syncthreads();
    }
    float inv = 1.f / red[0];
#pragma unroll
    for (int i = 0; i < VPT; i++) {
        float p = v[i] * inv;
        bf16 hh = __float2bfloat16(p);
        rh[tid + i * 256] = hh;
        rl[tid + i * 256] = __float2bfloat16(p - __bfloat162float(hh));
    }
}

// ---------------------------------------------------------------------------
// Launch.  Order arranged so launch index 5 (ncu -s 5 -c 1) is a GEMM.
// ---------------------------------------------------------------------------
extern "C" void kernel_launch(void* const* d_in, const int* in_sizes, int n_in,
                              void* d_out, int out_size) {
    const float* query = (const float*)d_in[0];
    const float* key_ = (const float*)d_in[1];
    const float* value = (const float*)d_in[2];
    const float* Qw = (const float*)d_in[3];
    const float* Kw = (const float*)d_in[4];
    const float* Vw = (const float*)d_in[5];
    const float* QA = (const float*)d_in[6];
    const float* QB = (const float*)d_in[7];
    const float* KA = (const float*)d_in[8];
    const float* KB = (const float*)d_in[9];
    const float* VA = (const float*)d_in[10];
    const float* VB = (const float*)d_in[11];
    const float* Ow = (const float*)d_in[12];
    float* out = (float*)d_out;

    cudaFuncSetAttribute(mma_gemm<0>, cudaFuncAttributeMaxDynamicSharedMemorySize, SMEM_DYN);
    cudaFuncSetAttribute(mma_gemm<1>, cudaFuncAttributeMaxDynamicSharedMemorySize, SMEM_DYN);
    cudaFuncSetAttribute(mma_gemm<2>, cudaFuncAttributeMaxDynamicSharedMemorySize, SMEM_DYN);
    cudaFuncSetAttribute(mma_gemm<3>, cudaFuncAttributeMaxDynamicSharedMemorySize, SMEM_DYN);

    float *pXAq, *pXAk, *pXAv, *pS;
    bf16 *qin_h, *qin_l, *kin_h, *kin_l, *vin_h, *vin_l;
    bf16 *qw_h, *qw_l, *kw_h, *kw_l, *vw_h, *vw_l, *ow_h, *ow_l;
    bf16 *Qh, *Ql, *Kh, *Kl, *VTh, *VTl, *Phh, *Pll, *Ohh, *Oll;
    cudaGetSymbolAddress((void**)&pXAq, g_XAq);
    cudaGetSymbolAddress((void**)&pXAk, g_XAk);
    cudaGetSymbolAddress((void**)&pXAv, g_XAv);
    cudaGetSymbolAddress((void**)&pS, g_S);
    cudaGetSymbolAddress((void**)&qin_h, g_qin_h);
    cudaGetSymbolAddress((void**)&qin_l, g_qin_l);
    cudaGetSymbolAddress((void**)&kin_h, g_kin_h);
    cudaGetSymbolAddress((void**)&kin_l, g_kin_l);
    cudaGetSymbolAddress((void**)&vin_h, g_vin_h);
    cudaGetSymbolAddress((void**)&vin_l, g_vin_l);
    cudaGetSymbolAddress((void**)&qw_h, g_qw_h);
    cudaGetSymbolAddress((void**)&qw_l, g_qw_l);
    cudaGetSymbolAddress((void**)&kw_h, g_kw_h);
    cudaGetSymbolAddress((void**)&kw_l, g_kw_l);
    cudaGetSymbolAddress((void**)&vw_h, g_vw_h);
    cudaGetSymbolAddress((void**)&vw_l, g_vw_l);
    cudaGetSymbolAddress((void**)&ow_h, g_ow_h);
    cudaGetSymbolAddress((void**)&ow_l, g_ow_l);
    cudaGetSymbolAddress((void**)&Qh, g_Qh);
    cudaGetSymbolAddress((void**)&Ql, g_Ql);
    cudaGetSymbolAddress((void**)&Kh, g_Kh);
    cudaGetSymbolAddress((void**)&Kl, g_Kl);
    cudaGetSymbolAddress((void**)&VTh, g_VTh);
    cudaGetSymbolAddress((void**)&VTl, g_VTl);
    cudaGetSymbolAddress((void**)&Phh, g_Ph);
    cudaGetSymbolAddress((void**)&Pll, g_Pl);
    cudaGetSymbolAddress((void**)&Ohh, g_Oh);
    cudaGetSymbolAddress((void**)&Oll, g_Ol);

    const long long nin4 = (long long)MTOT * EDIM / 4;
    const long long nw4 = (long long)EDIM * EDIM / 4;
    dim3 gproj(EDIM / 128, MTOT / 128, 1);

    // idx 0-4: Q-path preamble
    cvt_hilo_kernel<<<(int)(nin4 / 256), 256>>>(query, qin_h, qin_l, nin4);
    cvt_hilo_kernel<<<(int)(nw4 / 256), 256>>>(Qw, qw_h, qw_l, nw4);
    lora_xa_kernel<<<MTOT / 8, 256>>>(query, QA, pXAq, EDIM);
    cvt_hilo_kernel<<<(int)(nin4 / 256), 256>>>(key_, kin_h, kin_l, nin4);
    cvt_hilo_kernel<<<(int)(nw4 / 256), 256>>>(Kw, kw_h, kw_l, nw4);

    // idx 5: Q projection GEMM  (ncu -s 5 captures this one)
    mma_gemm<1><<<gproj, 256, SMEM_DYN>>>(qin_h, qin_l, qw_h, qw_l,
                                          EDIM, EDIM, EDIM, 0, 0, 0, 1.f,
                                          nullptr, Qh, Ql, EDIM, pXAq, QB);

    // idx 6-7: K path
    lora_xa_kernel<<<MTOT / 8, 256>>>(key_, KA, pXAk, EDIM);
    mma_gemm<1><<<gproj, 256, SMEM_DYN>>>(kin_h, kin_l, kw_h, kw_l,
                                          EDIM, EDIM, EDIM, 0, 0, 0, 1.f,
                                          nullptr, Kh, Kl, EDIM, pXAk, KB);

    // idx 8-11: V path
    cvt_hilo_kernel<<<(int)(nin4 / 256), 256>>>(value, vin_h, vin_l, nin4);
    cvt_hilo_kernel<<<(int)(nw4 / 256), 256>>>(Vw, vw_h, vw_l, nw4);
    lora_xa_kernel<<<MTOT / 8, 256>>>(value, VA, pXAv, EDIM);
    mma_gemm<2><<<gproj, 256, SMEM_DYN>>>(vin_h, vin_l, vw_h, vw_l,
                                          EDIM, EDIM, EDIM, 0, 0, 0, 1.f,
                                          nullptr, VTh, VTl, MTOT, pXAv, VB);

    // idx 12: O weight cvt
    cvt_hilo_kernel<<<(int)(nw4 / 256), 256>>>(Ow, ow_h, ow_l, nw4);

    // idx 13: scores = Q K^T / 32
    dim3 gsc(SDIM / 128, SDIM / 128, BATCH);
    mma_gemm<0><<<gsc, 256, SMEM_DYN>>>(Qh, Ql, Kh, Kl,
                                        EDIM, EDIM, EDIM,
                                        (long long)SDIM * EDIM,
                                        (long long)SDIM * EDIM,
                                        (long long)SDIM * SDIM,
                                        1.f / 32.f, pS, nullptr, nullptr, SDIM,
                                        nullptr, nullptr);

    // idx 14: softmax
    softmax_rows_kernel<<<BATCH * SDIM, 256>>>(pS, Phh, Pll);

    // idx 15: out = attn @ V
    dim3 gav(EDIM / 128, SDIM / 128, BATCH);
    mma_gemm<3><<<gav, 256, SMEM_DYN>>>(Phh, Pll, VTh, VTl,
                                        SDIM, SDIM, MTOT,
                                        (long long)SDIM * SDIM,
                                        (long long)SDIM,
                                        (long long)SDIM * EDIM,
                                        1.f, nullptr, Ohh, Oll, EDIM,
                                        nullptr, nullptr);

    // idx 16: final = out @ O^T -> d_out (fp32)
    mma_gemm<0><<<gproj, 256, SMEM_DYN>>>(Ohh, Oll, ow_h, ow_l,
                                          EDIM, EDIM, EDIM, 0, 0, 0, 1.f,
                                          out, nullptr, nullptr, EDIM,
                                          nullptr, nullptr);
}